// round 1
// baseline (speedup 1.0000x reference)
#include <cuda_runtime.h>
#include <cuda_bf16.h>

// LabelClusterLoss: loss over E[C0=512, T=128, C1=1024] fp32.
// Reduced to 4 streaming accumulators:
//   A_sq = sum(E^2)
//   A_R2 = sum over rows (i,t) of (rowsum over j)^2
//   A_C2 = sum over (t,j) of (colsum over i)^2
//   A_T2 = sum over t of (total sum of slice t)^2

#define T_DIM 128
#define C0_DIM 512
#define C1_DIM 1024

__device__ double g_acc[4];   // A_sq, A_R2, A_C2, A_T2

__global__ void init_acc_kernel() {
    if (threadIdx.x < 4) g_acc[threadIdx.x] = 0.0;
}

// Grid: 128 blocks (one per t). Block: 1024 threads = 32 warps.
// Warp w handles rows i = w + 32*k (k=0..15) of slice t.
// Thread (lane) owns columns {p*128 + lane*4 + c : p=0..7, c=0..3} -> colsum[32] regs.
__global__ void __launch_bounds__(1024, 1)
label_cluster_main(const float* __restrict__ A) {
    const int t    = blockIdx.x;
    const int w    = threadIdx.x >> 5;
    const int lane = threadIdx.x & 31;

    float colsum[32];
#pragma unroll
    for (int q = 0; q < 32; q++) colsum[q] = 0.0f;

    float sq_acc = 0.0f;   // partial sum of squares
    float r2_acc = 0.0f;   // partial sum of rowsum^2 (lane 0 only)

    for (int k = 0; k < 16; k++) {
        const int i = w + 32 * k;
        const float4* row =
            reinterpret_cast<const float4*>(A + (size_t)(i * T_DIM + t) * C1_DIM) + lane;
        float rs = 0.0f;
#pragma unroll
        for (int p = 0; p < 8; p++) {
            float4 v = row[p * 32];   // 512B contiguous per warp per load
            sq_acc = fmaf(v.x, v.x, sq_acc);
            sq_acc = fmaf(v.y, v.y, sq_acc);
            sq_acc = fmaf(v.z, v.z, sq_acc);
            sq_acc = fmaf(v.w, v.w, sq_acc);
            colsum[p * 4 + 0] += v.x;
            colsum[p * 4 + 1] += v.y;
            colsum[p * 4 + 2] += v.z;
            colsum[p * 4 + 3] += v.w;
            rs += (v.x + v.y) + (v.z + v.w);
        }
        // warp-reduce rowsum (xor tree -> all lanes hold full rowsum)
#pragma unroll
        for (int o = 16; o > 0; o >>= 1) rs += __shfl_xor_sync(0xFFFFFFFFu, rs, o);
        if (lane == 0) r2_acc = fmaf(rs, rs, r2_acc);
    }

    // ---- Cross-warp colsum tree reduction in shared (<=32KB) ----
    __shared__ float sbuf[8 * 1024];   // 32 KB

    // round: warps [src, src+n) store their 1024-col partials,
    //        warps [dst, dst+n) add them into their registers.
    struct Round { int src, dst, n; };
    const Round rounds[6] = {
        {16, 0, 8}, {24, 8, 8},   // 32 -> 16
        { 8, 0, 8},               // 16 -> 8
        { 4, 0, 4},               //  8 -> 4
        { 2, 0, 2},               //  4 -> 2
        { 1, 0, 1},               //  2 -> 1
    };
#pragma unroll
    for (int r = 0; r < 6; r++) {
        const int src = rounds[r].src, dst = rounds[r].dst, n = rounds[r].n;
        if (w >= src && w < src + n) {
            float* dstp = &sbuf[(w - src) * 1024];
#pragma unroll
            for (int p = 0; p < 8; p++) {
#pragma unroll
                for (int c = 0; c < 4; c++)
                    dstp[p * 128 + lane * 4 + c] = colsum[p * 4 + c];
            }
        }
        __syncthreads();
        if (w >= dst && w < dst + n) {
            const float* srcp = &sbuf[(w - dst) * 1024];
#pragma unroll
            for (int p = 0; p < 8; p++) {
#pragma unroll
                for (int c = 0; c < 4; c++)
                    colsum[p * 4 + c] += srcp[p * 128 + lane * 4 + c];
            }
        }
        __syncthreads();
    }
    // Warp 0 now holds the complete C[t, :] in its 32x32 registers.

    // ---- Block reduce sq_acc and r2_acc ----
    __shared__ float warp_sq[32];
    __shared__ float warp_r2[32];
    float s = sq_acc;
#pragma unroll
    for (int o = 16; o > 0; o >>= 1) s += __shfl_xor_sync(0xFFFFFFFFu, s, o);
    if (lane == 0) { warp_sq[w] = s; warp_r2[w] = r2_acc; }
    __syncthreads();

    if (w == 0) {
        // colsum stats
        float cs = 0.0f, cs2 = 0.0f;
#pragma unroll
        for (int q = 0; q < 32; q++) {
            cs += colsum[q];
            cs2 = fmaf(colsum[q], colsum[q], cs2);
        }
#pragma unroll
        for (int o = 16; o > 0; o >>= 1) {
            cs  += __shfl_xor_sync(0xFFFFFFFFu, cs, o);
            cs2 += __shfl_xor_sync(0xFFFFFFFFu, cs2, o);
        }
        // block totals of sq / r2
        float bsq = warp_sq[lane];
        float br2 = warp_r2[lane];
#pragma unroll
        for (int o = 16; o > 0; o >>= 1) {
            bsq += __shfl_xor_sync(0xFFFFFFFFu, bsq, o);
            br2 += __shfl_xor_sync(0xFFFFFFFFu, br2, o);
        }
        if (lane == 0) {
            atomicAdd(&g_acc[0], (double)bsq);
            atomicAdd(&g_acc[1], (double)br2);
            atomicAdd(&g_acc[2], (double)cs2);
            atomicAdd(&g_acc[3], (double)cs * (double)cs);
        }
    }
}

__global__ void finalize_kernel(float* __restrict__ out) {
    const double c0 = (double)C0_DIM, c1 = (double)C1_DIM;
    const double Asq = g_acc[0], AR2 = g_acc[1], AC2 = g_acc[2], AT2 = g_acc[3];
    const double cross = AT2 / (c0 * c1);
    const double intra  = Asq - AR2 / c1;
    const double inter  = AR2 / c1 - cross;
    const double dintra = Asq - AC2 / c0;
    const double dinter = AC2 / c0 - cross;
    const double loss = 0.5 * (intra / inter + dintra / dinter) / (c0 * c1);
    out[0] = (float)loss;
}

extern "C" void kernel_launch(void* const* d_in, const int* in_sizes, int n_in,
                              void* d_out, int out_size) {
    const float* A = (const float*)d_in[0];
    float* out = (float*)d_out;
    (void)in_sizes; (void)n_in; (void)out_size;

    init_acc_kernel<<<1, 32>>>();
    label_cluster_main<<<T_DIM, 1024>>>(A);
    finalize_kernel<<<1, 1>>>(out);
}